// round 10
// baseline (speedup 1.0000x reference)
#include <cuda_runtime.h>
#include <cuda_fp16.h>
#include <cstdint>
#include <cstddef>

#define S_LEN   64
#define N_SEQ   65536
#define RDIM    128
#define OUT_DIM 5
#define TILE    64
#define NTHREADS 256
#define SLOTS_PER_STEP 12               // 16KB slots: 2 halves x 6
#define TOTAL_SLOTS (S_LEN * SLOTS_PER_STEP)   // 768
#define SLOT_BYTES 16384                // two 8KB k16 sub-chunks
#define NBUF 4
#define APITCH 384                      // A row pitch bytes (192 k * 2B)

// ---- SMEM offsets (bytes), total 101440 -> 2 CTAs/SM ----
#define OFF_AHI   0          // 64*384 = 24576 (fp16: e | h)
#define OFF_B     24576      // 4 x 16384 = 65536
#define OFF_RED   90112      // 64*4*5 f32 = 5120
#define OFF_BIAS  95232      // 512 f32
#define OFF_WOUT  97280      // 640 f32
#define OFF_X     99840      // 128 f32
#define OFF_MASK  100352     // 64 i32
#define OFF_WEMB  100608     // 128 f32
#define OFF_BEMB  101120     // 64 f32
#define OFF_BOUT  101376     // 8 f32
#define OFF_MBAR  101408     // 4 x 8 mbarriers
#define SMEM_TOTAL 101440

// ---- device scratch ----
__device__ __align__(16) unsigned char g_Bstream[TOTAL_SLOTS / S_LEN * SLOT_BYTES]; // 192KB
__device__ float g_bias[512];

// ---- helpers ----
__device__ __forceinline__ uint32_t pack2h(float a, float b) {
    __half2 v = __floats2half2_rn(a, b);
    return *reinterpret_cast<uint32_t*>(&v);
}
__device__ __forceinline__ float sigf(float x) { return __fdividef(1.f, 1.f + __expf(-x)); }
__device__ __forceinline__ float tanh_(float x) { return fmaf(2.f, sigf(2.f * x), -1.f); }
// fast sigmoid: 1 MUFU via tanh.approx; abs err ~2.5e-4
__device__ __forceinline__ float sig_t(float x) {
    float t;
    asm("tanh.approx.f32 %0, %1;" : "=f"(t) : "f"(0.5f * x));
    return fmaf(0.5f, t, 0.5f);
}

#define MBINIT(a, c) asm volatile("mbarrier.init.shared.b64 [%0], %1;" :: "r"(a), "r"(c) : "memory")
#define MB_EXPECT_TX(a, bytes) asm volatile( \
    "mbarrier.arrive.expect_tx.shared.b64 _, [%0], %1;" :: "r"(a), "r"(bytes) : "memory")
#define BULK_G2S(dst, src, bytes, mbar) asm volatile( \
    "cp.async.bulk.shared::cluster.global.mbarrier::complete_tx::bytes [%0], [%1], %2, [%3];" \
    :: "r"(dst), "l"(src), "r"(bytes), "r"(mbar) : "memory")
#define FENCE_PROXY() asm volatile("fence.proxy.async.shared::cta;" ::: "memory")

#define MBAR_WAIT(mbar, par) do { \
    uint32_t _m = (mbar); uint32_t _p = (par); uint32_t _d; \
    asm volatile("{\n\t.reg .pred p;\n\t" \
        "mbarrier.try_wait.parity.acquire.cta.shared::cta.b64 p, [%1], %2;\n\t" \
        "selp.b32 %0, 1, 0, p;\n\t}" : "=r"(_d) : "r"(_m), "r"(_p) : "memory"); \
    if (!_d) { \
        asm volatile("{\n\t.reg .pred P1;\n\t" \
            "WL_%=:\n\t" \
            "mbarrier.try_wait.parity.acquire.cta.shared::cta.b64 P1, [%0], %1, 0x989680;\n\t" \
            "@P1 bra.uni WD_%=;\n\t" \
            "bra.uni WL_%=;\n\t" \
            "WD_%=:\n\t}" :: "r"(_m), "r"(_p) : "memory"); \
    } \
} while (0)

__device__ __forceinline__ void ldsm4(uint32_t* r, uint32_t addr) {
    asm volatile("ldmatrix.sync.aligned.m8n8.x4.shared.b16 {%0,%1,%2,%3}, [%4];"
        : "=r"(r[0]), "=r"(r[1]), "=r"(r[2]), "=r"(r[3]) : "r"(addr));
}
__device__ __forceinline__ void mma16816h(float* c, const uint32_t* a, uint32_t b0, uint32_t b1) {
    asm volatile("mma.sync.aligned.m16n8k16.row.col.f32.f16.f16.f32 "
        "{%0,%1,%2,%3}, {%4,%5,%6,%7}, {%8,%9}, {%0,%1,%2,%3};"
        : "+f"(c[0]), "+f"(c[1]), "+f"(c[2]), "+f"(c[3])
        : "r"(a[0]), "r"(a[1]), "r"(a[2]), "r"(a[3]), "r"(b0), "r"(b1));
}

// A byte address with per-row XOR swizzle (conflict-free ldmatrix at pitch 384)
__device__ __forceinline__ uint32_t a_addr(uint32_t base, int m, int kb) {
    uint32_t kb16 = (uint32_t)kb & ~15u, off = (uint32_t)kb & 15u;
    return base + (uint32_t)m * APITCH + (kb16 ^ (((uint32_t)m & 7u) << 4)) + off;
}

// ---- prep: B stream, fp16 (8KB sub-slot granularity; layout unchanged from R9) ----
__global__ void prep_w(const float* __restrict__ Wih, const float* __restrict__ Whh) {
    int idx = blockIdx.x * 128 + threadIdx.x;      // 0..6143
    int slot = idx >> 8, j = idx & 255;            // 24 old 8KB slots
    int nh = slot / 12, kc = slot % 12;
    int gi = (j & 3) * 128 + nh * 64 + (j >> 2);
    uint32_t hi[8];
    #pragma unroll
    for (int p = 0; p < 8; ++p) {
        int k0 = kc * 16 + p * 2;
        float w0 = (k0     < 64) ? Wih[gi * 64 + k0]     : Whh[gi * 128 + k0 - 64];
        float w1 = (k0 + 1 < 64) ? Wih[gi * 64 + k0 + 1] : Whh[gi * 128 + k0 + 1 - 64];
        hi[p] = pack2h(w0, w1);
    }
    uint4* base = (uint4*)(g_Bstream + (size_t)slot * 8192 + j * 16);
    base[0]         = make_uint4(hi[0], hi[1], hi[2], hi[3]);   // plane0
    base[4096 / 16] = make_uint4(hi[4], hi[5], hi[6], hi[7]);   // plane1
}
__global__ void prep_bias(const float* __restrict__ bih, const float* __restrict__ bhh) {
    int t = threadIdx.x; g_bias[t] = bih[t] + bhh[t];
}

// ---- main kernel: TILE=64, 256 threads, 2 CTAs/SM, c in registers ----
__global__ void __launch_bounds__(NTHREADS, 2)
lstm_mma(const float* __restrict__ input_data,
         const float* __restrict__ h0,
         const float* __restrict__ c0,
         const int*   __restrict__ ped_mask,
         const float* __restrict__ W_emb,
         const float* __restrict__ b_emb,
         const float* __restrict__ W_out,
         const float* __restrict__ b_out,
         float* __restrict__ out_y,
         float* __restrict__ out_h,
         float* __restrict__ out_c)
{
    extern __shared__ unsigned char smem[];
    const uint32_t sbase = (uint32_t)__cvta_generic_to_shared(smem);
    const int t = threadIdx.x, lane = t & 31, wid = t >> 5;     // 8 warps
    const int warp_m = wid >> 2, warp_n = wid & 3;              // 2 x 4
    const int n0 = blockIdx.x * TILE;
    const int odd = lane & 1;

    float* sRed  = (float*)(smem + OFF_RED);
    float* sBias = (float*)(smem + OFF_BIAS);
    float* sWout = (float*)(smem + OFF_WOUT);
    float* sX    = (float*)(smem + OFF_X);
    int*   sMask = (int*)  (smem + OFF_MASK);
    float* sWemb = (float*)(smem + OFF_WEMB);
    float* sBemb = (float*)(smem + OFF_BEMB);
    float* sBout = (float*)(smem + OFF_BOUT);

    // stage constants
    for (int i = t; i < 512; i += NTHREADS) sBias[i] = g_bias[i];
    for (int i = t; i < 640; i += NTHREADS) sWout[i] = W_out[i];
    if (t < 128) sWemb[t] = W_emb[t];
    else if (t < 192) sBemb[t - 128] = b_emb[t - 128];
    else if (t < 197) sBout[t - 192] = b_out[t - 192];

    // init mbarriers
    if (t == 0) {
        #pragma unroll
        for (int s = 0; s < NBUF; ++s) MBINIT(sbase + OFF_MBAR + s * 8, 1);
        FENCE_PROXY();
    }

    // init h -> A (fp16)
    {
        int m = t >> 2, rblk = (t & 3) * 32;
        const float4* hp = (const float4*)&h0[(size_t)(n0 + m) * RDIM + rblk];
        #pragma unroll
        for (int jj = 0; jj < 8; ++jj) {
            float4 hv = hp[jj];
            int r0 = rblk + jj * 4;
            uint32_t aH0 = a_addr(sbase + OFF_AHI, m, 128 + 2 * r0);
            uint32_t aH1 = a_addr(sbase + OFF_AHI, m, 128 + 2 * r0 + 4);
            asm volatile("st.shared.b32 [%0], %1;" :: "r"(aH0), "r"(pack2h(hv.x, hv.y)));
            asm volatile("st.shared.b32 [%0], %1;" :: "r"(aH1), "r"(pack2h(hv.z, hv.w)));
        }
    }

    // init c -> registers (mapping matches cell loop; step-invariant)
    float cre[32];
    {
        int mbase = warp_m * 32 + (lane >> 2) + (odd ? 8 : 0);
        int rbase = warp_n * 16 + ((lane & 3) >> 1);
        #pragma unroll
        for (int nh = 0; nh < 2; ++nh)
            #pragma unroll
            for (int mt = 0; mt < 2; ++mt)
                #pragma unroll
                for (int nt = 0; nt < 8; ++nt)
                    cre[nh * 16 + mt * 8 + nt] =
                        c0[(size_t)(n0 + mbase + mt * 16) * RDIM + nh * 64 + rbase + nt * 2];
    }
    __syncthreads();

    // prologue: slots 0,1,2 in flight via bulk copy (lead 3)
    if (t == 0) {
        #pragma unroll
        for (int s = 0; s < 3; ++s) {
            uint32_t mb = sbase + OFF_MBAR + (uint32_t)s * 8;
            MB_EXPECT_TX(mb, SLOT_BYTES);
            BULK_G2S(sbase + OFF_B + (uint32_t)s * SLOT_BYTES,
                     g_Bstream + (size_t)s * SLOT_BYTES, SLOT_BYTES, mb);
        }
    }

    __half2 hpend2[8];

    #pragma unroll 1
    for (int st = 0; st < S_LEN; ++st) {
        // stage x, mask
        if (t < 32) {
            ((float4*)sX)[t] = ((const float4*)(input_data + ((size_t)st * N_SEQ + n0) * 2))[t];
        } else if (t < 48) {
            ((int4*)sMask)[t - 32] = ((const int4*)(ped_mask + (size_t)st * N_SEQ + n0))[t - 32];
        }
        __syncthreads();

        // embedding -> A cols 0..63 (fp16)
        {
            int kp = lane, sg = wid;          // 8 warps x 8 seqs = 64
            float w00 = sWemb[kp * 4], w01 = sWemb[kp * 4 + 1];
            float w10 = sWemb[kp * 4 + 2], w11 = sWemb[kp * 4 + 3];
            float bb0 = sBemb[kp * 2], bb1 = sBemb[kp * 2 + 1];
            #pragma unroll
            for (int q = 0; q < 8; ++q) {
                int s2 = sg * 8 + q;
                float x0 = sX[s2 * 2], x1 = sX[s2 * 2 + 1];
                float e0 = fmaxf(fmaf(w00, x0, fmaf(w01, x1, bb0)), 0.f);
                float e1 = fmaxf(fmaf(w10, x0, fmaf(w11, x1, bb1)), 0.f);
                uint32_t aH = a_addr(sbase + OFF_AHI, s2, kp * 4);
                asm volatile("st.shared.b32 [%0], %1;" :: "r"(aH), "r"(pack2h(e0, e1)));
            }
        }

        // ---- two halves: gates for r in [nh*64, nh*64+64) ----
        #pragma unroll 1
        for (int nh = 0; nh < 2; ++nh) {
            float acc[2][8][4];
            #pragma unroll
            for (int a = 0; a < 2; ++a)
                #pragma unroll
                for (int b = 0; b < 8; ++b)
                    #pragma unroll
                    for (int d = 0; d < 4; ++d) acc[a][b][d] = 0.f;

            #pragma unroll 1
            for (int kcs = 0; kcs < 6; ++kcs) {          // 16KB slots
                int g = st * SLOTS_PER_STEP + nh * 6 + kcs;
                __syncthreads();       // reads of buffer (g+3)%NBUF (slot g-1) done
                int q = g + 3;
                if (t == 0 && q < TOTAL_SLOTS) {
                    uint32_t mb = sbase + OFF_MBAR + (uint32_t)(q % NBUF) * 8;
                    MB_EXPECT_TX(mb, SLOT_BYTES);
                    BULK_G2S(sbase + OFF_B + (uint32_t)(q % NBUF) * SLOT_BYTES,
                             g_Bstream + (size_t)(q % SLOTS_PER_STEP) * SLOT_BYTES,
                             SLOT_BYTES, mb);
                }
                MBAR_WAIT(sbase + OFF_MBAR + (uint32_t)(g % NBUF) * 8, (uint32_t)((g >> 2) & 1));
                uint32_t slotbase = sbase + OFF_B + (uint32_t)(g % NBUF) * SLOT_BYTES;

                #pragma unroll
                for (int sub = 0; sub < 2; ++sub) {
                    int kc = kcs * 2 + sub;              // k16 index within half
                    // A fragments for 2 m-tiles
                    uint32_t ah[2][4];
                    int arow = warp_m * 32 + (lane & 15);
                    int akb  = kc * 32 + ((lane >> 4) << 4);
                    ldsm4(ah[0], a_addr(sbase + OFF_AHI, arow, akb));
                    ldsm4(ah[1], a_addr(sbase + OFF_AHI, arow + 16, akb));
                    // B: 4 groups of 2 n8-tiles
                    uint32_t sbuf = slotbase + (uint32_t)sub * 8192u;
                    int msel = lane >> 3, r8 = lane & 7;
                    uint32_t brow_off = (uint32_t)(warp_n * 64 + ((msel >> 1) << 3) + r8) * 16u
                                      + (uint32_t)(msel & 1) * 4096u;
                    #pragma unroll
                    for (int p = 0; p < 4; ++p) {
                        uint32_t bh[4];
                        ldsm4(bh, sbuf + brow_off + (uint32_t)p * 256u);
                        #pragma unroll
                        for (int mt = 0; mt < 2; ++mt) {
                            mma16816h(acc[mt][2 * p],     ah[mt], bh[0], bh[1]);
                            mma16816h(acc[mt][2 * p + 1], ah[mt], bh[2], bh[3]);
                        }
                    }
                }
            }

            // ---- cell for this half (c in registers) ----
            #pragma unroll
            for (int mt = 0; mt < 2; ++mt) {
                #pragma unroll
                for (int nt = 0; nt < 8; ++nt) {
                    float c0v = acc[mt][nt][0], c1v = acc[mt][nt][1];
                    float c2v = acc[mt][nt][2], c3v = acc[mt][nt][3];
                    float e0 = __shfl_xor_sync(0xffffffffu, c0v, 1);
                    float e1 = __shfl_xor_sync(0xffffffffu, c1v, 1);
                    float e2 = __shfl_xor_sync(0xffffffffu, c2v, 1);
                    float e3 = __shfl_xor_sync(0xffffffffu, c3v, 1);
                    int mrow = warp_m * 32 + mt * 16 + (lane >> 2) + (odd ? 8 : 0);
                    int rl   = warp_n * 16 + nt * 2 + ((lane & 3) >> 1);
                    int r    = nh * 64 + rl;
                    float zi = (odd ? e2 : c0v) + sBias[r];
                    float zf = (odd ? e3 : c1v) + sBias[128 + r];
                    float zg = (odd ? c2v : e0) + sBias[256 + r];
                    float zo = (odd ? c3v : e1) + sBias[384 + r];
                    int ci = nh * 16 + mt * 8 + nt;
                    float co = cre[ci];
                    float cn = fmaf(sig_t(zf), co, sig_t(zi) * tanh_(zg));
                    float hn = sig_t(zo) * tanh_(cn);
                    int msk = sMask[mrow];
                    if (msk) cre[ci] = cn;
                    if (nh == 0) {
                        __half hh = __float2half_rn(hn);
                        if (nt & 1) hpend2[mt * 4 + (nt >> 1)].y = hh;
                        else        hpend2[mt * 4 + (nt >> 1)].x = hh;
                    } else if (msk) {
                        uint32_t aH = a_addr(sbase + OFF_AHI, mrow, 128 + 2 * r);
                        __half bh16 = __float2half_rn(hn);
                        asm volatile("st.shared.b16 [%0], %1;" :: "r"(aH), "h"(*(uint16_t*)&bh16));
                    }
                }
            }
        }

        // flush pending half-0 h writes (GEMMs done reading A)
        #pragma unroll
        for (int mt = 0; mt < 2; ++mt) {
            #pragma unroll
            for (int nt = 0; nt < 8; ++nt) {
                int mrow = warp_m * 32 + mt * 16 + (lane >> 2) + (odd ? 8 : 0);
                int r    = warp_n * 16 + nt * 2 + ((lane & 3) >> 1);
                if (sMask[mrow]) {
                    __half hh = (nt & 1) ? hpend2[mt * 4 + (nt >> 1)].y
                                         : hpend2[mt * 4 + (nt >> 1)].x;
                    uint32_t aH = a_addr(sbase + OFF_AHI, mrow, 128 + 2 * r);
                    asm volatile("st.shared.b16 [%0], %1;" :: "r"(aH), "h"(*(uint16_t*)&hh));
                }
            }
        }
        __syncthreads();

        // ---- output head (h from fp16 plane) ----
        {
            int s = t & 63, part = t >> 6;    // 4 parts x 32 r
            float o0 = 0, o1 = 0, o2 = 0, o3 = 0, o4 = 0;
            #pragma unroll
            for (int rr = 0; rr < 16; ++rr) {
                int r0 = part * 32 + rr * 2;
                uint32_t aH = a_addr(sbase + OFF_AHI, s, 128 + 2 * r0);
                uint32_t vh;
                asm volatile("ld.shared.b32 %0, [%1];" : "=r"(vh) : "r"(aH));
                __half2 h2 = *reinterpret_cast<__half2*>(&vh);
                float ha = __half2float(h2.x);
                float hb = __half2float(h2.y);
                o0 = fmaf(ha, sWout[r0], fmaf(hb, sWout[r0 + 1], o0));
                o1 = fmaf(ha, sWout[128 + r0], fmaf(hb, sWout[128 + r0 + 1], o1));
                o2 = fmaf(ha, sWout[256 + r0], fmaf(hb, sWout[256 + r0 + 1], o2));
                o3 = fmaf(ha, sWout[384 + r0], fmaf(hb, sWout[384 + r0 + 1], o3));
                o4 = fmaf(ha, sWout[512 + r0], fmaf(hb, sWout[512 + r0 + 1], o4));
            }
            float* rp = &sRed[(s * 4 + part) * 5];
            rp[0] = o0; rp[1] = o1; rp[2] = o2; rp[3] = o3; rp[4] = o4;
        }
        __syncthreads();
        for (int idx = t; idx < 320; idx += NTHREADS) {
            int s2 = idx / 5, oo = idx % 5;
            float v = 0.f;
            if (sMask[s2]) {
                v = sRed[(s2 * 4 + 0) * 5 + oo] + sRed[(s2 * 4 + 1) * 5 + oo]
                  + sRed[(s2 * 4 + 2) * 5 + oo] + sRed[(s2 * 4 + 3) * 5 + oo] + sBout[oo];
            }
            out_y[((size_t)st * N_SEQ + n0 + s2) * OUT_DIM + oo] = v;
        }
        __syncthreads();
    }

    // ---- final h writeback (from A plane) ----
    {
        int m = t >> 2, rblk = (t & 3) * 32;
        float4* hp = (float4*)&out_h[(size_t)(n0 + m) * RDIM + rblk];
        #pragma unroll
        for (int jj = 0; jj < 8; ++jj) {
            int r0 = rblk + jj * 4;
            uint32_t vh0, vh1;
            uint32_t aH0 = a_addr(sbase + OFF_AHI, m, 128 + 2 * r0);
            uint32_t aH1 = a_addr(sbase + OFF_AHI, m, 128 + 2 * r0 + 4);
            asm volatile("ld.shared.b32 %0, [%1];" : "=r"(vh0) : "r"(aH0));
            asm volatile("ld.shared.b32 %0, [%1];" : "=r"(vh1) : "r"(aH1));
            __half2 h2a = *reinterpret_cast<__half2*>(&vh0);
            __half2 h2b = *reinterpret_cast<__half2*>(&vh1);
            float4 hv;
            hv.x = __half2float(h2a.x);
            hv.y = __half2float(h2a.y);
            hv.z = __half2float(h2b.x);
            hv.w = __half2float(h2b.y);
            hp[jj] = hv;
        }
    }
    // ---- final c writeback (from registers) ----
    {
        int mbase = warp_m * 32 + (lane >> 2) + (odd ? 8 : 0);
        int rbase = warp_n * 16 + ((lane & 3) >> 1);
        #pragma unroll
        for (int nh = 0; nh < 2; ++nh)
            #pragma unroll
            for (int mt = 0; mt < 2; ++mt)
                #pragma unroll
                for (int nt = 0; nt < 8; ++nt)
                    out_c[(size_t)(n0 + mbase + mt * 16) * RDIM + nh * 64 + rbase + nt * 2] =
                        cre[nh * 16 + mt * 8 + nt];
    }
}

extern "C" void kernel_launch(void* const* d_in, const int* in_sizes, int n_in,
                              void* d_out, int out_size) {
    const float* input_data = (const float*)d_in[0];
    const float* h0         = (const float*)d_in[1];
    const float* c0         = (const float*)d_in[2];
    const int*   ped        = (const int*)  d_in[3];
    const float* W_emb      = (const float*)d_in[4];
    const float* b_emb      = (const float*)d_in[5];
    const float* W_ih       = (const float*)d_in[6];
    const float* W_hh       = (const float*)d_in[7];
    const float* b_ih       = (const float*)d_in[8];
    const float* b_hh       = (const float*)d_in[9];
    const float* W_out      = (const float*)d_in[10];
    const float* b_out      = (const float*)d_in[11];

    float* out   = (float*)d_out;
    float* out_y = out;                                      // [S][N][5]
    float* out_h = out + (size_t)S_LEN * N_SEQ * OUT_DIM;    // [N][128]
    float* out_c = out_h + (size_t)N_SEQ * RDIM;             // [N][128]

    prep_w<<<48, 128>>>(W_ih, W_hh);
    prep_bias<<<1, 512>>>(b_ih, b_hh);

    cudaFuncSetAttribute(lstm_mma, cudaFuncAttributeMaxDynamicSharedMemorySize, SMEM_TOTAL);
    lstm_mma<<<N_SEQ / TILE, NTHREADS, SMEM_TOTAL>>>(
        input_data, h0, c0, ped, W_emb, b_emb, W_out, b_out, out_y, out_h, out_c);
}

// round 11
// speedup vs baseline: 1.1986x; 1.1986x over previous
#include <cuda_runtime.h>
#include <cuda_fp16.h>
#include <cstdint>
#include <cstddef>

#define S_LEN   64
#define N_SEQ   65536
#define RDIM    128
#define OUT_DIM 5
#define TILE    64
#define NTHREADS 256
#define KDIM    192
#define NKC     12                      // k16 chunks per half
#define SLOTS_PER_STEP 24               // 2 halves x 12 kc
#define TOTAL_SLOTS (S_LEN * SLOTS_PER_STEP)   // 1536
#define SLOT_BYTES 8192                 // fp16: plane0 (k0-7) + plane1 (k8-15)
#define NBUF 4
#define APITCH 384                      // A row pitch bytes (192 k * 2B)

// ---- SMEM offsets (bytes), total 101440 -> 2 CTAs/SM ----
#define OFF_AHI   0          // 64*384 = 24576 (fp16 hi: e | h)
#define OFF_B     24576      // 4 x 8192 = 32768
#define OFF_C     57344      // 64*128 f32 = 32768
#define OFF_RED   90112      // 64*4*5 f32 = 5120
#define OFF_BIAS  95232      // 512 f32
#define OFF_WOUT  97280      // 640 f32
#define OFF_X     99840      // 128 f32
#define OFF_MASK  100352     // 64 i32
#define OFF_WEMB  100608     // 128 f32
#define OFF_BEMB  101120     // 64 f32
#define OFF_BOUT  101376     // 8 f32
#define OFF_MBAR  101408     // 4 x 8 mbarriers
#define SMEM_TOTAL 101440

// ---- device scratch ----
__device__ __align__(16) unsigned char g_Bstream[SLOTS_PER_STEP * SLOT_BYTES]; // 192KB
__device__ float g_bias[512];

// ---- helpers ----
__device__ __forceinline__ uint32_t pack2h(float a, float b) {
    __half2 v = __floats2half2_rn(a, b);
    return *reinterpret_cast<uint32_t*>(&v);
}
// 1-MUFU transcendentals (validated error-neutral in R10 for sigmoid)
__device__ __forceinline__ float tanh_a(float x) {
    float t;
    asm("tanh.approx.f32 %0, %1;" : "=f"(t) : "f"(x));
    return t;
}
__device__ __forceinline__ float sig_t(float x) {
    float t;
    asm("tanh.approx.f32 %0, %1;" : "=f"(t) : "f"(0.5f * x));
    return fmaf(0.5f, t, 0.5f);
}

#define MBINIT(a, c) asm volatile("mbarrier.init.shared.b64 [%0], %1;" :: "r"(a), "r"(c) : "memory")
#define MB_EXPECT_TX(a, bytes) asm volatile( \
    "mbarrier.arrive.expect_tx.shared.b64 _, [%0], %1;" :: "r"(a), "r"(bytes) : "memory")
#define BULK_G2S(dst, src, bytes, mbar) asm volatile( \
    "cp.async.bulk.shared::cluster.global.mbarrier::complete_tx::bytes [%0], [%1], %2, [%3];" \
    :: "r"(dst), "l"(src), "r"(bytes), "r"(mbar) : "memory")
#define FENCE_PROXY() asm volatile("fence.proxy.async.shared::cta;" ::: "memory")

#define MBAR_WAIT(mbar, par) do { \
    uint32_t _m = (mbar); uint32_t _p = (par); uint32_t _d; \
    asm volatile("{\n\t.reg .pred p;\n\t" \
        "mbarrier.try_wait.parity.acquire.cta.shared::cta.b64 p, [%1], %2;\n\t" \
        "selp.b32 %0, 1, 0, p;\n\t}" : "=r"(_d) : "r"(_m), "r"(_p) : "memory"); \
    if (!_d) { \
        asm volatile("{\n\t.reg .pred P1;\n\t" \
            "WL_%=:\n\t" \
            "mbarrier.try_wait.parity.acquire.cta.shared::cta.b64 P1, [%0], %1, 0x989680;\n\t" \
            "@P1 bra.uni WD_%=;\n\t" \
            "bra.uni WL_%=;\n\t" \
            "WD_%=:\n\t}" :: "r"(_m), "r"(_p) : "memory"); \
    } \
} while (0)

__device__ __forceinline__ void ldsm4(uint32_t* r, uint32_t addr) {
    asm volatile("ldmatrix.sync.aligned.m8n8.x4.shared.b16 {%0,%1,%2,%3}, [%4];"
        : "=r"(r[0]), "=r"(r[1]), "=r"(r[2]), "=r"(r[3]) : "r"(addr));
}
__device__ __forceinline__ void mma16816h(float* c, const uint32_t* a, uint32_t b0, uint32_t b1) {
    asm volatile("mma.sync.aligned.m16n8k16.row.col.f32.f16.f16.f32 "
        "{%0,%1,%2,%3}, {%4,%5,%6,%7}, {%8,%9}, {%0,%1,%2,%3};"
        : "+f"(c[0]), "+f"(c[1]), "+f"(c[2]), "+f"(c[3])
        : "r"(a[0]), "r"(a[1]), "r"(a[2]), "r"(a[3]), "r"(b0), "r"(b1));
}

// A byte address with per-row XOR swizzle (conflict-free ldmatrix at pitch 384)
__device__ __forceinline__ uint32_t a_addr(uint32_t base, int m, int kb) {
    uint32_t kb16 = (uint32_t)kb & ~15u, off = (uint32_t)kb & 15u;
    return base + (uint32_t)m * APITCH + (kb16 ^ (((uint32_t)m & 7u) << 4)) + off;
}

// ---- prep: B stream, fp16. slot = nh*12+kc. Row j (0..255): r_local=j>>2, gate=j&3.
// Layout per slot: [0,4K) k0-7 | [4K,8K) k8-15
__global__ void prep_w(const float* __restrict__ Wih, const float* __restrict__ Whh) {
    int idx = blockIdx.x * 128 + threadIdx.x;      // 0..6143
    int slot = idx >> 8, j = idx & 255;
    int nh = slot / 12, kc = slot % 12;
    int gi = (j & 3) * 128 + nh * 64 + (j >> 2);
    uint32_t hi[8];
    #pragma unroll
    for (int p = 0; p < 8; ++p) {
        int k0 = kc * 16 + p * 2;
        float w0 = (k0     < 64) ? Wih[gi * 64 + k0]     : Whh[gi * 128 + k0 - 64];
        float w1 = (k0 + 1 < 64) ? Wih[gi * 64 + k0 + 1] : Whh[gi * 128 + k0 + 1 - 64];
        hi[p] = pack2h(w0, w1);
    }
    uint4* base = (uint4*)(g_Bstream + (size_t)slot * SLOT_BYTES + j * 16);
    base[0]         = make_uint4(hi[0], hi[1], hi[2], hi[3]);   // plane0
    base[4096 / 16] = make_uint4(hi[4], hi[5], hi[6], hi[7]);   // plane1
}
__global__ void prep_bias(const float* __restrict__ bih, const float* __restrict__ bhh) {
    int t = threadIdx.x; g_bias[t] = bih[t] + bhh[t];
}

// ---- main kernel: TILE=64, 256 threads, 2 CTAs/SM, bulk-copied B stream ----
__global__ void __launch_bounds__(NTHREADS, 2)
lstm_mma(const float* __restrict__ input_data,
         const float* __restrict__ h0,
         const float* __restrict__ c0,
         const int*   __restrict__ ped_mask,
         const float* __restrict__ W_emb,
         const float* __restrict__ b_emb,
         const float* __restrict__ W_out,
         const float* __restrict__ b_out,
         float* __restrict__ out_y,
         float* __restrict__ out_h,
         float* __restrict__ out_c)
{
    extern __shared__ unsigned char smem[];
    const uint32_t sbase = (uint32_t)__cvta_generic_to_shared(smem);
    const int t = threadIdx.x, lane = t & 31, wid = t >> 5;     // 8 warps
    const int warp_m = wid >> 2, warp_n = wid & 3;              // 2 x 4
    const int n0 = blockIdx.x * TILE;

    float* sC    = (float*)(smem + OFF_C);
    float* sRed  = (float*)(smem + OFF_RED);
    float* sBias = (float*)(smem + OFF_BIAS);
    float* sWout = (float*)(smem + OFF_WOUT);
    float* sX    = (float*)(smem + OFF_X);
    int*   sMask = (int*)  (smem + OFF_MASK);
    float* sWemb = (float*)(smem + OFF_WEMB);
    float* sBemb = (float*)(smem + OFF_BEMB);
    float* sBout = (float*)(smem + OFF_BOUT);

    // stage constants
    for (int i = t; i < 512; i += NTHREADS) sBias[i] = g_bias[i];
    for (int i = t; i < 640; i += NTHREADS) sWout[i] = W_out[i];
    if (t < 128) sWemb[t] = W_emb[t];
    else if (t < 192) sBemb[t - 128] = b_emb[t - 128];
    else if (t < 197) sBout[t - 192] = b_out[t - 192];

    // init mbarriers
    if (t == 0) {
        #pragma unroll
        for (int s = 0; s < NBUF; ++s) MBINIT(sbase + OFF_MBAR + s * 8, 1);
        FENCE_PROXY();
    }

    // init h -> A (fp16 hi), c -> sC
    {
        int m = t >> 2, rblk = (t & 3) * 32;
        const float4* hp = (const float4*)&h0[(size_t)(n0 + m) * RDIM + rblk];
        const float4* cp = (const float4*)&c0[(size_t)(n0 + m) * RDIM + rblk];
        #pragma unroll
        for (int jj = 0; jj < 8; ++jj) {
            float4 hv = hp[jj], cv = cp[jj];
            *(float4*)&sC[m * 128 + rblk + jj * 4] = cv;
            int r0 = rblk + jj * 4;
            uint32_t aH0 = a_addr(sbase + OFF_AHI, m, 128 + 2 * r0);
            uint32_t aH1 = a_addr(sbase + OFF_AHI, m, 128 + 2 * r0 + 4);
            asm volatile("st.shared.b32 [%0], %1;" :: "r"(aH0), "r"(pack2h(hv.x, hv.y)));
            asm volatile("st.shared.b32 [%0], %1;" :: "r"(aH1), "r"(pack2h(hv.z, hv.w)));
        }
    }
    __syncthreads();

    // prologue: slots 0,1,2 in flight via bulk copy
    if (t == 0) {
        #pragma unroll
        for (int s = 0; s < 3; ++s) {
            uint32_t mb = sbase + OFF_MBAR + (uint32_t)s * 8;
            MB_EXPECT_TX(mb, SLOT_BYTES);
            BULK_G2S(sbase + OFF_B + (uint32_t)s * SLOT_BYTES,
                     g_Bstream + (size_t)s * SLOT_BYTES, SLOT_BYTES, mb);
        }
    }

    float hpend[16];

    #pragma unroll 1
    for (int st = 0; st < S_LEN; ++st) {
        // stage x, mask
        if (t < 32) {
            ((float4*)sX)[t] = ((const float4*)(input_data + ((size_t)st * N_SEQ + n0) * 2))[t];
        } else if (t < 48) {
            ((int4*)sMask)[t - 32] = ((const int4*)(ped_mask + (size_t)st * N_SEQ + n0))[t - 32];
        }
        __syncthreads();

        // embedding -> A cols 0..63 (fp16 hi)
        {
            int kp = lane, sg = wid;          // 8 warps x 8 seqs = 64
            float w00 = sWemb[kp * 4], w01 = sWemb[kp * 4 + 1];
            float w10 = sWemb[kp * 4 + 2], w11 = sWemb[kp * 4 + 3];
            float bb0 = sBemb[kp * 2], bb1 = sBemb[kp * 2 + 1];
            #pragma unroll
            for (int q = 0; q < 8; ++q) {
                int s2 = sg * 8 + q;
                float x0 = sX[s2 * 2], x1 = sX[s2 * 2 + 1];
                float e0 = fmaxf(fmaf(w00, x0, fmaf(w01, x1, bb0)), 0.f);
                float e1 = fmaxf(fmaf(w10, x0, fmaf(w11, x1, bb1)), 0.f);
                uint32_t aH = a_addr(sbase + OFF_AHI, s2, kp * 4);
                asm volatile("st.shared.b32 [%0], %1;" :: "r"(aH), "r"(pack2h(e0, e1)));
            }
        }

        // ---- two halves: gates for r in [nh*64, nh*64+64) ----
        #pragma unroll 1
        for (int nh = 0; nh < 2; ++nh) {
            float acc[2][8][4];
            #pragma unroll
            for (int a = 0; a < 2; ++a)
                #pragma unroll
                for (int b = 0; b < 8; ++b)
                    #pragma unroll
                    for (int d = 0; d < 4; ++d) acc[a][b][d] = 0.f;

            #pragma unroll 1
            for (int kc = 0; kc < NKC; ++kc) {
                int g = st * SLOTS_PER_STEP + nh * NKC + kc;
                __syncthreads();       // all reads of buffer (g+3)%NBUF (slot g-1) done
                int q = g + 3;
                if (t == 0 && q < TOTAL_SLOTS) {
                    uint32_t mb = sbase + OFF_MBAR + (uint32_t)(q % NBUF) * 8;
                    MB_EXPECT_TX(mb, SLOT_BYTES);
                    BULK_G2S(sbase + OFF_B + (uint32_t)(q % NBUF) * SLOT_BYTES,
                             g_Bstream + (size_t)(q % SLOTS_PER_STEP) * SLOT_BYTES,
                             SLOT_BYTES, mb);
                }
                MBAR_WAIT(sbase + OFF_MBAR + (uint32_t)(g % NBUF) * 8, (uint32_t)((g >> 2) & 1));
                uint32_t sbuf = sbase + OFF_B + (uint32_t)(g % NBUF) * SLOT_BYTES;

                // A fragments (hi only) for 2 m-tiles
                uint32_t ah[2][4];
                int arow = warp_m * 32 + (lane & 15);
                int akb  = kc * 32 + ((lane >> 4) << 4);
                ldsm4(ah[0], a_addr(sbase + OFF_AHI, arow, akb));
                ldsm4(ah[1], a_addr(sbase + OFF_AHI, arow + 16, akb));
                // B: 4 groups of 2 n8-tiles
                int msel = lane >> 3, r8 = lane & 7;
                uint32_t brow_off = (uint32_t)(warp_n * 64 + ((msel >> 1) << 3) + r8) * 16u
                                  + (uint32_t)(msel & 1) * 4096u;
                #pragma unroll
                for (int p = 0; p < 4; ++p) {
                    uint32_t bh[4];
                    ldsm4(bh, sbuf + brow_off + (uint32_t)p * 256u);
                    #pragma unroll
                    for (int mt = 0; mt < 2; ++mt) {
                        mma16816h(acc[mt][2 * p],     ah[mt], bh[0], bh[1]);
                        mma16816h(acc[mt][2 * p + 1], ah[mt], bh[2], bh[3]);
                    }
                }
            }

            // ---- cell for this half ----
            const int odd = lane & 1;
            #pragma unroll
            for (int mt = 0; mt < 2; ++mt) {
                #pragma unroll
                for (int nt = 0; nt < 8; ++nt) {
                    float c0v = acc[mt][nt][0], c1v = acc[mt][nt][1];
                    float c2v = acc[mt][nt][2], c3v = acc[mt][nt][3];
                    float e0 = __shfl_xor_sync(0xffffffffu, c0v, 1);
                    float e1 = __shfl_xor_sync(0xffffffffu, c1v, 1);
                    float e2 = __shfl_xor_sync(0xffffffffu, c2v, 1);
                    float e3 = __shfl_xor_sync(0xffffffffu, c3v, 1);
                    int mrow = warp_m * 32 + mt * 16 + (lane >> 2) + (odd ? 8 : 0);
                    int rl   = warp_n * 16 + nt * 2 + ((lane & 3) >> 1);
                    int r    = nh * 64 + rl;
                    float zi = (odd ? e2 : c0v) + sBias[r];
                    float zf = (odd ? e3 : c1v) + sBias[128 + r];
                    float zg = (odd ? c2v : e0) + sBias[256 + r];
                    float zo = (odd ? c3v : e1) + sBias[384 + r];
                    float co = sC[mrow * 128 + r];
                    float cn = fmaf(sig_t(zf), co, sig_t(zi) * tanh_a(zg));
                    float hn = sig_t(zo) * tanh_a(cn);
                    int msk = sMask[mrow];
                    if (msk) sC[mrow * 128 + r] = cn;
                    if (nh == 0) {
                        hpend[mt * 8 + nt] = hn;
                    } else if (msk) {
                        uint32_t aH = a_addr(sbase + OFF_AHI, mrow, 128 + 2 * r);
                        __half bh16 = __float2half_rn(hn);
                        asm volatile("st.shared.b16 [%0], %1;" :: "r"(aH), "h"(*(uint16_t*)&bh16));
                    }
                }
            }
        }

        // flush pending half-0 h writes (GEMMs done reading A)
        #pragma unroll
        for (int mt = 0; mt < 2; ++mt) {
            #pragma unroll
            for (int nt = 0; nt < 8; ++nt) {
                int mrow = warp_m * 32 + mt * 16 + (lane >> 2) + ((lane & 1) ? 8 : 0);
                int r    = warp_n * 16 + nt * 2 + ((lane & 3) >> 1);
                if (sMask[mrow]) {
                    uint32_t aH = a_addr(sbase + OFF_AHI, mrow, 128 + 2 * r);
                    __half bh16 = __float2half_rn(hpend[mt * 8 + nt]);
                    asm volatile("st.shared.b16 [%0], %1;" :: "r"(aH), "h"(*(uint16_t*)&bh16));
                }
            }
        }
        __syncthreads();

        // ---- output head (h from fp16-hi plane) ----
        {
            int s = t & 63, part = t >> 6;    // 4 parts x 32 r
            float o0 = 0, o1 = 0, o2 = 0, o3 = 0, o4 = 0;
            #pragma unroll
            for (int rr = 0; rr < 16; ++rr) {
                int r0 = part * 32 + rr * 2;
                uint32_t aH = a_addr(sbase + OFF_AHI, s, 128 + 2 * r0);
                uint32_t vh;
                asm volatile("ld.shared.b32 %0, [%1];" : "=r"(vh) : "r"(aH));
                __half2 h2 = *reinterpret_cast<__half2*>(&vh);
                float ha = __half2float(h2.x);
                float hb = __half2float(h2.y);
                o0 = fmaf(ha, sWout[r0], fmaf(hb, sWout[r0 + 1], o0));
                o1 = fmaf(ha, sWout[128 + r0], fmaf(hb, sWout[128 + r0 + 1], o1));
                o2 = fmaf(ha, sWout[256 + r0], fmaf(hb, sWout[256 + r0 + 1], o2));
                o3 = fmaf(ha, sWout[384 + r0], fmaf(hb, sWout[384 + r0 + 1], o3));
                o4 = fmaf(ha, sWout[512 + r0], fmaf(hb, sWout[512 + r0 + 1], o4));
            }
            float* rp = &sRed[(s * 4 + part) * 5];
            rp[0] = o0; rp[1] = o1; rp[2] = o2; rp[3] = o3; rp[4] = o4;
        }
        __syncthreads();
        for (int idx = t; idx < 320; idx += NTHREADS) {
            int s2 = idx / 5, oo = idx % 5;
            float v = 0.f;
            if (sMask[s2]) {
                v = sRed[(s2 * 4 + 0) * 5 + oo] + sRed[(s2 * 4 + 1) * 5 + oo]
                  + sRed[(s2 * 4 + 2) * 5 + oo] + sRed[(s2 * 4 + 3) * 5 + oo] + sBout[oo];
            }
            out_y[((size_t)st * N_SEQ + n0 + s2) * OUT_DIM + oo] = v;
        }
        __syncthreads();
    }

    // ---- final h, c writeback ----
    {
        int m = t >> 2, rblk = (t & 3) * 32;
        float4* hp = (float4*)&out_h[(size_t)(n0 + m) * RDIM + rblk];
        float4* cp = (float4*)&out_c[(size_t)(n0 + m) * RDIM + rblk];
        #pragma unroll
        for (int jj = 0; jj < 8; ++jj) {
            int r0 = rblk + jj * 4;
            uint32_t vh0, vh1;
            uint32_t aH0 = a_addr(sbase + OFF_AHI, m, 128 + 2 * r0);
            uint32_t aH1 = a_addr(sbase + OFF_AHI, m, 128 + 2 * r0 + 4);
            asm volatile("ld.shared.b32 %0, [%1];" : "=r"(vh0) : "r"(aH0));
            asm volatile("ld.shared.b32 %0, [%1];" : "=r"(vh1) : "r"(aH1));
            __half2 h2a = *reinterpret_cast<__half2*>(&vh0);
            __half2 h2b = *reinterpret_cast<__half2*>(&vh1);
            float4 hv;
            hv.x = __half2float(h2a.x);
            hv.y = __half2float(h2a.y);
            hv.z = __half2float(h2b.x);
            hv.w = __half2float(h2b.y);
            hp[jj] = hv;
            cp[jj] = *(float4*)&sC[m * 128 + r0];
        }
    }
}

extern "C" void kernel_launch(void* const* d_in, const int* in_sizes, int n_in,
                              void* d_out, int out_size) {
    const float* input_data = (const float*)d_in[0];
    const float* h0         = (const float*)d_in[1];
    const float* c0         = (const float*)d_in[2];
    const int*   ped        = (const int*)  d_in[3];
    const float* W_emb      = (const float*)d_in[4];
    const float* b_emb      = (const float*)d_in[5];
    const float* W_ih       = (const float*)d_in[6];
    const float* W_hh       = (const float*)d_in[7];
    const float* b_ih       = (const float*)d_in[8];
    const float* b_hh       = (const float*)d_in[9];
    const float* W_out      = (const float*)d_in[10];
    const float* b_out      = (const float*)d_in[11];

    float* out   = (float*)d_out;
    float* out_y = out;                                      // [S][N][5]
    float* out_h = out + (size_t)S_LEN * N_SEQ * OUT_DIM;    // [N][128]
    float* out_c = out_h + (size_t)N_SEQ * RDIM;             // [N][128]

    prep_w<<<48, 128>>>(W_ih, W_hh);
    prep_bias<<<1, 512>>>(b_ih, b_hh);

    cudaFuncSetAttribute(lstm_mma, cudaFuncAttributeMaxDynamicSharedMemorySize, SMEM_TOTAL);
    lstm_mma<<<N_SEQ / TILE, NTHREADS, SMEM_TOTAL>>>(
        input_data, h0, c0, ped, W_emb, b_emb, W_out, b_out, out_y, out_h, out_c);
}

// round 12
// speedup vs baseline: 1.3963x; 1.1649x over previous
#include <cuda_runtime.h>
#include <cuda_fp16.h>
#include <cstdint>
#include <cstddef>

#define S_LEN   64
#define N_SEQ   65536
#define RDIM    128
#define OUT_DIM 5
#define TILE    64
#define NTHREADS 256
#define SLOTS_PER_STEP 12               // 16KB slots: 2 halves x 6
#define TOTAL_SLOTS (S_LEN * SLOTS_PER_STEP)   // 768
#define SLOT_BYTES 16384                // two 8KB k16 sub-chunks
#define NBUF 3
#define APITCH 384                      // A row pitch bytes (192 k * 2B)

// ---- SMEM offsets (bytes), total 112192 -> 2 CTAs/SM ----
#define OFF_AHI   0          // 64*384 = 24576 (fp16: e | h)
#define OFF_B     24576      // 3 x 16384 = 49152
#define OFF_C     73728      // 64*128 f32 = 32768
#define OFF_BIAS  106496     // 512 f32 = 2048
#define OFF_WOUT  108544     // 8 x 128 fp16 = 2048 (rows 5..7 zero)
#define OFF_X     110592     // 128 f32 = 512
#define OFF_MASK  111104     // 64 i32 = 256
#define OFF_WEMB  111360     // 128 f32 = 512
#define OFF_BEMB  111872     // 64 f32 = 256
#define OFF_BOUT  112128     // 8 f32 = 32
#define OFF_MBAR  112160     // 3 x 8 mbarriers (pad 32)
#define SMEM_TOTAL 112192

// ---- device scratch ----
__device__ __align__(16) unsigned char g_Bstream[SLOTS_PER_STEP * SLOT_BYTES]; // 192KB
__device__ float g_bias[512];

// ---- helpers ----
__device__ __forceinline__ uint32_t pack2h(float a, float b) {
    __half2 v = __floats2half2_rn(a, b);
    return *reinterpret_cast<uint32_t*>(&v);
}
// 1-MUFU transcendentals (validated error-neutral R10/R11)
__device__ __forceinline__ float tanh_a(float x) {
    float t;
    asm("tanh.approx.f32 %0, %1;" : "=f"(t) : "f"(x));
    return t;
}
__device__ __forceinline__ float sig_t(float x) {
    float t;
    asm("tanh.approx.f32 %0, %1;" : "=f"(t) : "f"(0.5f * x));
    return fmaf(0.5f, t, 0.5f);
}

#define MBINIT(a, c) asm volatile("mbarrier.init.shared.b64 [%0], %1;" :: "r"(a), "r"(c) : "memory")
#define MB_EXPECT_TX(a, bytes) asm volatile( \
    "mbarrier.arrive.expect_tx.shared.b64 _, [%0], %1;" :: "r"(a), "r"(bytes) : "memory")
#define BULK_G2S(dst, src, bytes, mbar) asm volatile( \
    "cp.async.bulk.shared::cluster.global.mbarrier::complete_tx::bytes [%0], [%1], %2, [%3];" \
    :: "r"(dst), "l"(src), "r"(bytes), "r"(mbar) : "memory")
#define FENCE_PROXY() asm volatile("fence.proxy.async.shared::cta;" ::: "memory")

#define MBAR_WAIT(mbar, par) do { \
    uint32_t _m = (mbar); uint32_t _p = (par); uint32_t _d; \
    asm volatile("{\n\t.reg .pred p;\n\t" \
        "mbarrier.try_wait.parity.acquire.cta.shared::cta.b64 p, [%1], %2;\n\t" \
        "selp.b32 %0, 1, 0, p;\n\t}" : "=r"(_d) : "r"(_m), "r"(_p) : "memory"); \
    if (!_d) { \
        asm volatile("{\n\t.reg .pred P1;\n\t" \
            "WL_%=:\n\t" \
            "mbarrier.try_wait.parity.acquire.cta.shared::cta.b64 P1, [%0], %1, 0x989680;\n\t" \
            "@P1 bra.uni WD_%=;\n\t" \
            "bra.uni WL_%=;\n\t" \
            "WD_%=:\n\t}" :: "r"(_m), "r"(_p) : "memory"); \
    } \
} while (0)

__device__ __forceinline__ void ldsm4(uint32_t* r, uint32_t addr) {
    asm volatile("ldmatrix.sync.aligned.m8n8.x4.shared.b16 {%0,%1,%2,%3}, [%4];"
        : "=r"(r[0]), "=r"(r[1]), "=r"(r[2]), "=r"(r[3]) : "r"(addr));
}
__device__ __forceinline__ void mma16816h(float* c, const uint32_t* a, uint32_t b0, uint32_t b1) {
    asm volatile("mma.sync.aligned.m16n8k16.row.col.f32.f16.f16.f32 "
        "{%0,%1,%2,%3}, {%4,%5,%6,%7}, {%8,%9}, {%0,%1,%2,%3};"
        : "+f"(c[0]), "+f"(c[1]), "+f"(c[2]), "+f"(c[3])
        : "r"(a[0]), "r"(a[1]), "r"(a[2]), "r"(a[3]), "r"(b0), "r"(b1));
}

// A byte address with per-row XOR swizzle (conflict-free ldmatrix at pitch 384)
__device__ __forceinline__ uint32_t a_addr(uint32_t base, int m, int kb) {
    uint32_t kb16 = (uint32_t)kb & ~15u, off = (uint32_t)kb & 15u;
    return base + (uint32_t)m * APITCH + (kb16 ^ (((uint32_t)m & 7u) << 4)) + off;
}

// ---- prep: B stream, fp16 (layout identical to R11; 16KB slot = 2 consecutive 8KB) ----
__global__ void prep_w(const float* __restrict__ Wih, const float* __restrict__ Whh) {
    int idx = blockIdx.x * 128 + threadIdx.x;      // 0..6143
    int slot = idx >> 8, j = idx & 255;            // 24 8KB sub-slots
    int nh = slot / 12, kc = slot % 12;
    int gi = (j & 3) * 128 + nh * 64 + (j >> 2);
    uint32_t hi[8];
    #pragma unroll
    for (int p = 0; p < 8; ++p) {
        int k0 = kc * 16 + p * 2;
        float w0 = (k0     < 64) ? Wih[gi * 64 + k0]     : Whh[gi * 128 + k0 - 64];
        float w1 = (k0 + 1 < 64) ? Wih[gi * 64 + k0 + 1] : Whh[gi * 128 + k0 + 1 - 64];
        hi[p] = pack2h(w0, w1);
    }
    uint4* base = (uint4*)(g_Bstream + (size_t)slot * 8192 + j * 16);
    base[0]         = make_uint4(hi[0], hi[1], hi[2], hi[3]);   // plane0
    base[4096 / 16] = make_uint4(hi[4], hi[5], hi[6], hi[7]);   // plane1
}
__global__ void prep_bias(const float* __restrict__ bih, const float* __restrict__ bhh) {
    int t = threadIdx.x; g_bias[t] = bih[t] + bhh[t];
}

// ---- main kernel ----
__global__ void __launch_bounds__(NTHREADS, 2)
lstm_mma(const float* __restrict__ input_data,
         const float* __restrict__ h0,
         const float* __restrict__ c0,
         const int*   __restrict__ ped_mask,
         const float* __restrict__ W_emb,
         const float* __restrict__ b_emb,
         const float* __restrict__ W_out,
         const float* __restrict__ b_out,
         float* __restrict__ out_y,
         float* __restrict__ out_h,
         float* __restrict__ out_c)
{
    extern __shared__ unsigned char smem[];
    const uint32_t sbase = (uint32_t)__cvta_generic_to_shared(smem);
    const int t = threadIdx.x, lane = t & 31, wid = t >> 5;     // 8 warps
    const int warp_m = wid >> 2, warp_n = wid & 3;              // 2 x 4
    const int n0 = blockIdx.x * TILE;

    float* sC    = (float*)(smem + OFF_C);
    float* sBias = (float*)(smem + OFF_BIAS);
    float* sX    = (float*)(smem + OFF_X);
    int*   sMask = (int*)  (smem + OFF_MASK);
    float* sWemb = (float*)(smem + OFF_WEMB);
    float* sBemb = (float*)(smem + OFF_BEMB);
    float* sBout = (float*)(smem + OFF_BOUT);

    // stage constants
    for (int i = t; i < 512; i += NTHREADS) sBias[i] = g_bias[i];
    // W_out fp16, [8 rows][128 k], rows 5..7 zero
    for (int i = t; i < 512; i += NTHREADS) {     // 512 half2 pairs
        int n = i >> 6, k0 = (i & 63) * 2;
        float w0 = (n < OUT_DIM) ? W_out[n * RDIM + k0]     : 0.f;
        float w1 = (n < OUT_DIM) ? W_out[n * RDIM + k0 + 1] : 0.f;
        *(uint32_t*)(smem + OFF_WOUT + (uint32_t)i * 4u) = pack2h(w0, w1);
    }
    if (t < 128) sWemb[t] = W_emb[t];
    else if (t < 192) sBemb[t - 128] = b_emb[t - 128];
    else if (t < 197) sBout[t - 192] = b_out[t - 192];

    // init mbarriers
    if (t == 0) {
        #pragma unroll
        for (int s = 0; s < NBUF; ++s) MBINIT(sbase + OFF_MBAR + s * 8, 1);
        FENCE_PROXY();
    }

    // init h -> A (fp16), c -> sC
    {
        int m = t >> 2, rblk = (t & 3) * 32;
        const float4* hp = (const float4*)&h0[(size_t)(n0 + m) * RDIM + rblk];
        const float4* cp = (const float4*)&c0[(size_t)(n0 + m) * RDIM + rblk];
        #pragma unroll
        for (int jj = 0; jj < 8; ++jj) {
            float4 hv = hp[jj], cv = cp[jj];
            *(float4*)&sC[m * 128 + rblk + jj * 4] = cv;
            int r0 = rblk + jj * 4;
            uint32_t aH0 = a_addr(sbase + OFF_AHI, m, 128 + 2 * r0);
            uint32_t aH1 = a_addr(sbase + OFF_AHI, m, 128 + 2 * r0 + 4);
            asm volatile("st.shared.b32 [%0], %1;" :: "r"(aH0), "r"(pack2h(hv.x, hv.y)));
            asm volatile("st.shared.b32 [%0], %1;" :: "r"(aH1), "r"(pack2h(hv.z, hv.w)));
        }
    }
    __syncthreads();

    // prologue: slots 0,1 in flight (lead 2, NBUF=3)
    if (t == 0) {
        #pragma unroll
        for (int s = 0; s < 2; ++s) {
            uint32_t mb = sbase + OFF_MBAR + (uint32_t)s * 8;
            MB_EXPECT_TX(mb, SLOT_BYTES);
            BULK_G2S(sbase + OFF_B + (uint32_t)s * SLOT_BYTES,
                     g_Bstream + (size_t)s * SLOT_BYTES, SLOT_BYTES, mb);
        }
    }

    float hpend[16];

    #pragma unroll 1
    for (int st = 0; st < S_LEN; ++st) {
        // stage x, mask (mask of prev step consumed before last loop-end sync)
        if (t < 32) {
            ((float4*)sX)[t] = ((const float4*)(input_data + ((size_t)st * N_SEQ + n0) * 2))[t];
        } else if (t < 48) {
            ((int4*)sMask)[t - 32] = ((const int4*)(ped_mask + (size_t)st * N_SEQ + n0))[t - 32];
        }
        __syncthreads();

        // embedding -> A cols 0..63 (fp16)
        {
            int kp = lane, sg = wid;          // 8 warps x 8 seqs = 64
            float w00 = sWemb[kp * 4], w01 = sWemb[kp * 4 + 1];
            float w10 = sWemb[kp * 4 + 2], w11 = sWemb[kp * 4 + 3];
            float bb0 = sBemb[kp * 2], bb1 = sBemb[kp * 2 + 1];
            #pragma unroll
            for (int q = 0; q < 8; ++q) {
                int s2 = sg * 8 + q;
                float x0 = sX[s2 * 2], x1 = sX[s2 * 2 + 1];
                float e0 = fmaxf(fmaf(w00, x0, fmaf(w01, x1, bb0)), 0.f);
                float e1 = fmaxf(fmaf(w10, x0, fmaf(w11, x1, bb1)), 0.f);
                uint32_t aH = a_addr(sbase + OFF_AHI, s2, kp * 4);
                asm volatile("st.shared.b32 [%0], %1;" :: "r"(aH), "r"(pack2h(e0, e1)));
            }
        }

        // ---- two halves: gates for r in [nh*64, nh*64+64) ----
        #pragma unroll 1
        for (int nh = 0; nh < 2; ++nh) {
            float acc[2][8][4];
            #pragma unroll
            for (int a = 0; a < 2; ++a)
                #pragma unroll
                for (int b = 0; b < 8; ++b)
                    #pragma unroll
                    for (int d = 0; d < 4; ++d) acc[a][b][d] = 0.f;

            #pragma unroll 1
            for (int kcs = 0; kcs < 6; ++kcs) {          // 16KB slots
                int g = st * SLOTS_PER_STEP + nh * 6 + kcs;
                __syncthreads();       // reads of slot g-1 (buffer (g+2)%3) done
                int q = g + 2;
                if (t == 0 && q < TOTAL_SLOTS) {
                    uint32_t mb = sbase + OFF_MBAR + (uint32_t)(q % NBUF) * 8;
                    MB_EXPECT_TX(mb, SLOT_BYTES);
                    BULK_G2S(sbase + OFF_B + (uint32_t)(q % NBUF) * SLOT_BYTES,
                             g_Bstream + (size_t)(q % SLOTS_PER_STEP) * SLOT_BYTES,
                             SLOT_BYTES, mb);
                }
                MBAR_WAIT(sbase + OFF_MBAR + (uint32_t)(g % NBUF) * 8,
                          (uint32_t)((g / NBUF) & 1));
                uint32_t slotbase = sbase + OFF_B + (uint32_t)(g % NBUF) * SLOT_BYTES;

                #pragma unroll
                for (int sub = 0; sub < 2; ++sub) {
                    int kc = kcs * 2 + sub;              // k16 index within half
                    uint32_t ah[2][4];
                    int arow = warp_m * 32 + (lane & 15);
                    int akb  = kc * 32 + ((lane >> 4) << 4);
                    ldsm4(ah[0], a_addr(sbase + OFF_AHI, arow, akb));
                    ldsm4(ah[1], a_addr(sbase + OFF_AHI, arow + 16, akb));
                    uint32_t sbuf = slotbase + (uint32_t)sub * 8192u;
                    int msel = lane >> 3, r8 = lane & 7;
                    uint32_t brow_off = (uint32_t)(warp_n * 64 + ((msel >> 1) << 3) + r8) * 16u
                                      + (uint32_t)(msel & 1) * 4096u;
                    #pragma unroll
                    for (int p = 0; p < 4; ++p) {
                        uint32_t bh[4];
                        ldsm4(bh, sbuf + brow_off + (uint32_t)p * 256u);
                        #pragma unroll
                        for (int mt = 0; mt < 2; ++mt) {
                            mma16816h(acc[mt][2 * p],     ah[mt], bh[0], bh[1]);
                            mma16816h(acc[mt][2 * p + 1], ah[mt], bh[2], bh[3]);
                        }
                    }
                }
            }

            // ---- cell for this half ----
            const int odd = lane & 1;
            #pragma unroll
            for (int mt = 0; mt < 2; ++mt) {
                #pragma unroll
                for (int nt = 0; nt < 8; ++nt) {
                    float c0v = acc[mt][nt][0], c1v = acc[mt][nt][1];
                    float c2v = acc[mt][nt][2], c3v = acc[mt][nt][3];
                    float e0 = __shfl_xor_sync(0xffffffffu, c0v, 1);
                    float e1 = __shfl_xor_sync(0xffffffffu, c1v, 1);
                    float e2 = __shfl_xor_sync(0xffffffffu, c2v, 1);
                    float e3 = __shfl_xor_sync(0xffffffffu, c3v, 1);
                    int mrow = warp_m * 32 + mt * 16 + (lane >> 2) + (odd ? 8 : 0);
                    int rl   = warp_n * 16 + nt * 2 + ((lane & 3) >> 1);
                    int r    = nh * 64 + rl;
                    float zi = (odd ? e2 : c0v) + sBias[r];
                    float zf = (odd ? e3 : c1v) + sBias[128 + r];
                    float zg = (odd ? c2v : e0) + sBias[256 + r];
                    float zo = (odd ? c3v : e1) + sBias[384 + r];
                    float co = sC[mrow * 128 + r];
                    float cn = fmaf(sig_t(zf), co, sig_t(zi) * tanh_a(zg));
                    float hn = sig_t(zo) * tanh_a(cn);
                    int msk = sMask[mrow];
                    if (msk) sC[mrow * 128 + r] = cn;
                    if (nh == 0) {
                        hpend[mt * 8 + nt] = hn;
                    } else if (msk) {
                        uint32_t aH = a_addr(sbase + OFF_AHI, mrow, 128 + 2 * r);
                        __half bh16 = __float2half_rn(hn);
                        asm volatile("st.shared.b16 [%0], %1;" :: "r"(aH), "h"(*(uint16_t*)&bh16));
                    }
                }
            }
        }

        // flush pending half-0 h writes (GEMMs done reading A)
        #pragma unroll
        for (int mt = 0; mt < 2; ++mt) {
            #pragma unroll
            for (int nt = 0; nt < 8; ++nt) {
                int mrow = warp_m * 32 + mt * 16 + (lane >> 2) + ((lane & 1) ? 8 : 0);
                int r    = warp_n * 16 + nt * 2 + ((lane & 3) >> 1);
                if (sMask[mrow]) {
                    uint32_t aH = a_addr(sbase + OFF_AHI, mrow, 128 + 2 * r);
                    __half bh16 = __float2half_rn(hpend[mt * 8 + nt]);
                    asm volatile("st.shared.b16 [%0], %1;" :: "r"(aH), "h"(*(uint16_t*)&bh16));
                }
            }
        }
        __syncthreads();     // h_t complete in A plane

        // ---- fused output head: warps 0-3, one m16 tile each; K=128, N=8 (5 used) ----
        if (wid < 4) {
            float oacc[4] = {0.f, 0.f, 0.f, 0.f};
            uint32_t wbase = sbase + OFF_WOUT + (uint32_t)(lane >> 2) * 256u
                           + (uint32_t)(lane & 3) * 4u;
            int arow = wid * 16 + (lane & 15);
            #pragma unroll
            for (int kc = 0; kc < 8; ++kc) {
                uint32_t ah[4];
                int akb = 128 + kc * 32 + ((lane >> 4) << 4);
                ldsm4(ah, a_addr(sbase + OFF_AHI, arow, akb));
                uint32_t b0, b1;
                asm volatile("ld.shared.b32 %0, [%1];" : "=r"(b0) : "r"(wbase + kc * 32u));
                asm volatile("ld.shared.b32 %0, [%1];" : "=r"(b1) : "r"(wbase + kc * 32u + 16u));
                mma16816h(oacc, ah, b0, b1);
            }
            int r0 = wid * 16 + (lane >> 2);
            int cn0 = (lane & 3) * 2;
            int m0 = sMask[r0], m1 = sMask[r0 + 8];
            float* yp0 = &out_y[((size_t)st * N_SEQ + n0 + r0) * OUT_DIM];
            float* yp1 = &out_y[((size_t)st * N_SEQ + n0 + r0 + 8) * OUT_DIM];
            if (cn0 < OUT_DIM) {
                yp0[cn0] = m0 ? oacc[0] + sBout[cn0] : 0.f;
                yp1[cn0] = m1 ? oacc[2] + sBout[cn0] : 0.f;
            }
            if (cn0 + 1 < OUT_DIM) {
                yp0[cn0 + 1] = m0 ? oacc[1] + sBout[cn0 + 1] : 0.f;
                yp1[cn0 + 1] = m1 ? oacc[3] + sBout[cn0 + 1] : 0.f;
            }
        }
        __syncthreads();     // head done with sMask before next restage
    }

    // ---- final h, c writeback ----
    {
        int m = t >> 2, rblk = (t & 3) * 32;
        float4* hp = (float4*)&out_h[(size_t)(n0 + m) * RDIM + rblk];
        float4* cp = (float4*)&out_c[(size_t)(n0 + m) * RDIM + rblk];
        #pragma unroll
        for (int jj = 0; jj < 8; ++jj) {
            int r0 = rblk + jj * 4;
            uint32_t vh0, vh1;
            uint32_t aH0 = a_addr(sbase + OFF_AHI, m, 128 + 2 * r0);
            uint32_t aH1 = a_addr(sbase + OFF_AHI, m, 128 + 2 * r0 + 4);
            asm volatile("ld.shared.b32 %0, [%1];" : "=r"(vh0) : "r"(aH0));
            asm volatile("ld.shared.b32 %0, [%1];" : "=r"(vh1) : "r"(aH1));
            __half2 h2a = *reinterpret_cast<__half2*>(&vh0);
            __half2 h2b = *reinterpret_cast<__half2*>(&vh1);
            float4 hv;
            hv.x = __half2float(h2a.x);
            hv.y = __half2float(h2a.y);
            hv.z = __half2float(h2b.x);
            hv.w = __half2float(h2b.y);
            hp[jj] = hv;
            cp[jj] = *(float4*)&sC[m * 128 + r0];
        }
    }
}

extern "C" void kernel_launch(void* const* d_in, const int* in_sizes, int n_in,
                              void* d_out, int out_size) {
    const float* input_data = (const float*)d_in[0];
    const float* h0         = (const float*)d_in[1];
    const float* c0         = (const float*)d_in[2];
    const int*   ped        = (const int*)  d_in[3];
    const float* W_emb      = (const float*)d_in[4];
    const float* b_emb      = (const float*)d_in[5];
    const float* W_ih       = (const float*)d_in[6];
    const float* W_hh       = (const float*)d_in[7];
    const float* b_ih       = (const float*)d_in[8];
    const float* b_hh       = (const float*)d_in[9];
    const float* W_out      = (const float*)d_in[10];
    const float* b_out      = (const float*)d_in[11];

    float* out   = (float*)d_out;
    float* out_y = out;                                      // [S][N][5]
    float* out_h = out + (size_t)S_LEN * N_SEQ * OUT_DIM;    // [N][128]
    float* out_c = out_h + (size_t)N_SEQ * RDIM;             // [N][128]

    prep_w<<<48, 128>>>(W_ih, W_hh);
    prep_bias<<<1, 512>>>(b_ih, b_hh);

    cudaFuncSetAttribute(lstm_mma, cudaFuncAttributeMaxDynamicSharedMemorySize, SMEM_TOTAL);
    lstm_mma<<<N_SEQ / TILE, NTHREADS, SMEM_TOTAL>>>(
        input_data, h0, c0, ped, W_emb, b_emb, W_out, b_out, out_y, out_h, out_c);
}

// round 14
// speedup vs baseline: 1.3987x; 1.0017x over previous
#include <cuda_runtime.h>
#include <cuda_fp16.h>
#include <cstdint>
#include <cstddef>

#define S_LEN   64
#define N_SEQ   65536
#define RDIM    128
#define OUT_DIM 5
#define TILE    64
#define NTHREADS 256
#define SLOTS_PER_STEP 12               // 16KB slots: 2 halves x 6
#define TOTAL_SLOTS (S_LEN * SLOTS_PER_STEP)   // 768
#define SLOT_BYTES 16384                // two 8KB k16 sub-chunks
#define NBUF 3
#define APITCH 384                      // A row pitch bytes (192 k * 2B)

// ---- SMEM offsets (bytes), total 112192 -> 2 CTAs/SM ----
#define OFF_AHI   0          // 64*384 = 24576 (fp16: e | h)
#define OFF_B     24576      // 3 x 16384 = 49152
#define OFF_C     73728      // 64*128 f32 = 32768
#define OFF_BIAS  106496     // 512 f32 = 2048
#define OFF_WOUT  108544     // 8 x 128 fp16 = 2048 (rows 5..7 zero)
#define OFF_X     110592     // 128 f32 = 512
#define OFF_MASK  111104     // 64 i32 = 256
#define OFF_WEMB  111360     // 128 f32 = 512
#define OFF_BEMB  111872     // 64 f32 = 256
#define OFF_BOUT  112128     // 8 f32 = 32
#define OFF_MBAR  112160     // 3 x 8 mbarriers (pad 32)
#define SMEM_TOTAL 112192

// ---- device scratch ----
__device__ __align__(16) unsigned char g_Bstream[SLOTS_PER_STEP * SLOT_BYTES]; // 192KB
__device__ float g_bias[512];

// ---- helpers ----
__device__ __forceinline__ uint32_t pack2h(float a, float b) {
    __half2 v = __floats2half2_rn(a, b);
    return *reinterpret_cast<uint32_t*>(&v);
}
// 1-MUFU transcendentals (validated error-neutral R10/R11)
__device__ __forceinline__ float tanh_a(float x) {
    float t;
    asm("tanh.approx.f32 %0, %1;" : "=f"(t) : "f"(x));
    return t;
}
__device__ __forceinline__ float sig_t(float x) {
    float t;
    asm("tanh.approx.f32 %0, %1;" : "=f"(t) : "f"(0.5f * x));
    return fmaf(0.5f, t, 0.5f);
}

#define MBINIT(a, c) asm volatile("mbarrier.init.shared.b64 [%0], %1;" :: "r"(a), "r"(c) : "memory")
#define MB_EXPECT_TX(a, bytes) asm volatile( \
    "mbarrier.arrive.expect_tx.shared.b64 _, [%0], %1;" :: "r"(a), "r"(bytes) : "memory")
#define BULK_G2S(dst, src, bytes, mbar) asm volatile( \
    "cp.async.bulk.shared::cluster.global.mbarrier::complete_tx::bytes [%0], [%1], %2, [%3];" \
    :: "r"(dst), "l"(src), "r"(bytes), "r"(mbar) : "memory")
#define FENCE_PROXY() asm volatile("fence.proxy.async.shared::cta;" ::: "memory")

#define MBAR_WAIT(mbar, par) do { \
    uint32_t _m = (mbar); uint32_t _p = (par); uint32_t _d; \
    asm volatile("{\n\t.reg .pred p;\n\t" \
        "mbarrier.try_wait.parity.acquire.cta.shared::cta.b64 p, [%1], %2;\n\t" \
        "selp.b32 %0, 1, 0, p;\n\t}" : "=r"(_d) : "r"(_m), "r"(_p) : "memory"); \
    if (!_d) { \
        asm volatile("{\n\t.reg .pred P1;\n\t" \
            "WL_%=:\n\t" \
            "mbarrier.try_wait.parity.acquire.cta.shared::cta.b64 P1, [%0], %1, 0x989680;\n\t" \
            "@P1 bra.uni WD_%=;\n\t" \
            "bra.uni WL_%=;\n\t" \
            "WD_%=:\n\t}" :: "r"(_m), "r"(_p) : "memory"); \
    } \
} while (0)

__device__ __forceinline__ void ldsm4(uint32_t* r, uint32_t addr) {
    asm volatile("ldmatrix.sync.aligned.m8n8.x4.shared.b16 {%0,%1,%2,%3}, [%4];"
        : "=r"(r[0]), "=r"(r[1]), "=r"(r[2]), "=r"(r[3]) : "r"(addr));
}
__device__ __forceinline__ void mma16816h(float* c, const uint32_t* a, uint32_t b0, uint32_t b1) {
    asm volatile("mma.sync.aligned.m16n8k16.row.col.f32.f16.f16.f32 "
        "{%0,%1,%2,%3}, {%4,%5,%6,%7}, {%8,%9}, {%0,%1,%2,%3};"
        : "+f"(c[0]), "+f"(c[1]), "+f"(c[2]), "+f"(c[3])
        : "r"(a[0]), "r"(a[1]), "r"(a[2]), "r"(a[3]), "r"(b0), "r"(b1));
}

// A byte address with per-row XOR swizzle (conflict-free ldmatrix at pitch 384)
__device__ __forceinline__ uint32_t a_addr(uint32_t base, int m, int kb) {
    uint32_t kb16 = (uint32_t)kb & ~15u, off = (uint32_t)kb & 15u;
    return base + (uint32_t)m * APITCH + (kb16 ^ (((uint32_t)m & 7u) << 4)) + off;
}

// ---- prep: B stream, fp16 (16KB slot = 2 consecutive 8KB k16 sub-chunks) ----
__global__ void prep_w(const float* __restrict__ Wih, const float* __restrict__ Whh) {
    int idx = blockIdx.x * 128 + threadIdx.x;      // 0..6143
    int slot = idx >> 8, j = idx & 255;            // 24 8KB sub-slots
    int nh = slot / 12, kc = slot % 12;
    int gi = (j & 3) * 128 + nh * 64 + (j >> 2);
    uint32_t hi[8];
    #pragma unroll
    for (int p = 0; p < 8; ++p) {
        int k0 = kc * 16 + p * 2;
        float w0 = (k0     < 64) ? Wih[gi * 64 + k0]     : Whh[gi * 128 + k0 - 64];
        float w1 = (k0 + 1 < 64) ? Wih[gi * 64 + k0 + 1] : Whh[gi * 128 + k0 + 1 - 64];
        hi[p] = pack2h(w0, w1);
    }
    uint4* base = (uint4*)(g_Bstream + (size_t)slot * 8192 + j * 16);
    base[0]         = make_uint4(hi[0], hi[1], hi[2], hi[3]);   // plane0
    base[4096 / 16] = make_uint4(hi[4], hi[5], hi[6], hi[7]);   // plane1
}
__global__ void prep_bias(const float* __restrict__ bih, const float* __restrict__ bhh) {
    int t = threadIdx.x; g_bias[t] = bih[t] + bhh[t];
}

// ---- main kernel ----
__global__ void __launch_bounds__(NTHREADS, 2)
lstm_mma(const float* __restrict__ input_data,
         const float* __restrict__ h0,
         const float* __restrict__ c0,
         const int*   __restrict__ ped_mask,
         const float* __restrict__ W_emb,
         const float* __restrict__ b_emb,
         const float* __restrict__ W_out,
         const float* __restrict__ b_out,
         float* __restrict__ out_y,
         float* __restrict__ out_h,
         float* __restrict__ out_c)
{
    extern __shared__ unsigned char smem[];
    const uint32_t sbase = (uint32_t)__cvta_generic_to_shared(smem);
    const int t = threadIdx.x, lane = t & 31, wid = t >> 5;     // 8 warps
    const int warp_m = wid >> 2, warp_n = wid & 3;              // 2 x 4
    const int n0 = blockIdx.x * TILE;

    float* sC    = (float*)(smem + OFF_C);
    float* sBias = (float*)(smem + OFF_BIAS);
    float* sX    = (float*)(smem + OFF_X);
    int*   sMask = (int*)  (smem + OFF_MASK);
    float* sWemb = (float*)(smem + OFF_WEMB);
    float* sBemb = (float*)(smem + OFF_BEMB);
    float* sBout = (float*)(smem + OFF_BOUT);

    // stage constants
    for (int i = t; i < 512; i += NTHREADS) sBias[i] = g_bias[i];
    // W_out fp16, [8 rows][128 k], rows 5..7 zero
    for (int i = t; i < 512; i += NTHREADS) {     // 512 half2 pairs
        int n = i >> 6, k0 = (i & 63) * 2;
        float w0 = (n < OUT_DIM) ? W_out[n * RDIM + k0]     : 0.f;
        float w1 = (n < OUT_DIM) ? W_out[n * RDIM + k0 + 1] : 0.f;
        *(uint32_t*)(smem + OFF_WOUT + (uint32_t)i * 4u) = pack2h(w0, w1);
    }
    if (t < 128) sWemb[t] = W_emb[t];
    else if (t < 192) sBemb[t - 128] = b_emb[t - 128];
    else if (t < 197) sBout[t - 192] = b_out[t - 192];

    // init mbarriers
    if (t == 0) {
        #pragma unroll
        for (int s = 0; s < NBUF; ++s) MBINIT(sbase + OFF_MBAR + s * 8, 1);
        FENCE_PROXY();
    }

    // init h -> A (fp16), c -> sC
    {
        int m = t >> 2, rblk = (t & 3) * 32;
        const float4* hp = (const float4*)&h0[(size_t)(n0 + m) * RDIM + rblk];
        const float4* cp = (const float4*)&c0[(size_t)(n0 + m) * RDIM + rblk];
        #pragma unroll
        for (int jj = 0; jj < 8; ++jj) {
            float4 hv = hp[jj], cv = cp[jj];
            *(float4*)&sC[m * 128 + rblk + jj * 4] = cv;
            int r0 = rblk + jj * 4;
            uint32_t aH0 = a_addr(sbase + OFF_AHI, m, 128 + 2 * r0);
            uint32_t aH1 = a_addr(sbase + OFF_AHI, m, 128 + 2 * r0 + 4);
            asm volatile("st.shared.b32 [%0], %1;" :: "r"(aH0), "r"(pack2h(hv.x, hv.y)));
            asm volatile("st.shared.b32 [%0], %1;" :: "r"(aH1), "r"(pack2h(hv.z, hv.w)));
        }
    }
    __syncthreads();

    // anti-phase stagger: first-wave-B CTAs delay ~half a step once, so the two
    // co-resident CTAs run GEMM and cell phases out of phase. Pure scheduling;
    // no effect on numerics or determinism of results.
    if (blockIdx.x >= 148 && blockIdx.x < 296) {
        unsigned long long s0 = clock64();
        while (clock64() - s0 < 16384ull) {}
    }

    // prologue: slots 0,1 in flight (lead 2, NBUF=3)
    if (t == 0) {
        #pragma unroll
        for (int s = 0; s < 2; ++s) {
            uint32_t mb = sbase + OFF_MBAR + (uint32_t)s * 8;
            MB_EXPECT_TX(mb, SLOT_BYTES);
            BULK_G2S(sbase + OFF_B + (uint32_t)s * SLOT_BYTES,
                     g_Bstream + (size_t)s * SLOT_BYTES, SLOT_BYTES, mb);
        }
    }

    float hpend[16];

    #pragma unroll 1
    for (int st = 0; st < S_LEN; ++st) {
        // stage x, mask
        if (t < 32) {
            ((float4*)sX)[t] = ((const float4*)(input_data + ((size_t)st * N_SEQ + n0) * 2))[t];
        } else if (t < 48) {
            ((int4*)sMask)[t - 32] = ((const int4*)(ped_mask + (size_t)st * N_SEQ + n0))[t - 32];
        }
        __syncthreads();

        // embedding -> A cols 0..63 (fp16)
        {
            int kp = lane, sg = wid;          // 8 warps x 8 seqs = 64
            float w00 = sWemb[kp * 4], w01 = sWemb[kp * 4 + 1];
            float w10 = sWemb[kp * 4 + 2], w11 = sWemb[kp * 4 + 3];
            float bb0 = sBemb[kp * 2], bb1 = sBemb[kp * 2 + 1];
            #pragma unroll
            for (int q = 0; q < 8; ++q) {
                int s2 = sg * 8 + q;
                float x0 = sX[s2 * 2], x1 = sX[s2 * 2 + 1];
                float e0 = fmaxf(fmaf(w00, x0, fmaf(w01, x1, bb0)), 0.f);
                float e1 = fmaxf(fmaf(w10, x0, fmaf(w11, x1, bb1)), 0.f);
                uint32_t aH = a_addr(sbase + OFF_AHI, s2, kp * 4);
                asm volatile("st.shared.b32 [%0], %1;" :: "r"(aH), "r"(pack2h(e0, e1)));
            }
        }

        // ---- two halves: gates for r in [nh*64, nh*64+64) ----
        #pragma unroll 1
        for (int nh = 0; nh < 2; ++nh) {
            float acc[2][8][4];
            #pragma unroll
            for (int a = 0; a < 2; ++a)
                #pragma unroll
                for (int b = 0; b < 8; ++b)
                    #pragma unroll
                    for (int d = 0; d < 4; ++d) acc[a][b][d] = 0.f;

            #pragma unroll 1
            for (int kcs = 0; kcs < 6; ++kcs) {          // 16KB slots
                int g = st * SLOTS_PER_STEP + nh * 6 + kcs;
                __syncthreads();       // reads of slot g-1 (buffer (g+2)%3) done; A-plane WAR order
                int q = g + 2;
                if (t == 0 && q < TOTAL_SLOTS) {
                    uint32_t mb = sbase + OFF_MBAR + (uint32_t)(q % NBUF) * 8;
                    MB_EXPECT_TX(mb, SLOT_BYTES);
                    BULK_G2S(sbase + OFF_B + (uint32_t)(q % NBUF) * SLOT_BYTES,
                             g_Bstream + (size_t)(q % SLOTS_PER_STEP) * SLOT_BYTES,
                             SLOT_BYTES, mb);
                }
                MBAR_WAIT(sbase + OFF_MBAR + (uint32_t)(g % NBUF) * 8,
                          (uint32_t)((g / NBUF) & 1));
                uint32_t slotbase = sbase + OFF_B + (uint32_t)(g % NBUF) * SLOT_BYTES;

                #pragma unroll
                for (int sub = 0; sub < 2; ++sub) {
                    int kc = kcs * 2 + sub;              // k16 index within half
                    uint32_t ah[2][4];
                    int arow = warp_m * 32 + (lane & 15);
                    int akb  = kc * 32 + ((lane >> 4) << 4);
                    ldsm4(ah[0], a_addr(sbase + OFF_AHI, arow, akb));
                    ldsm4(ah[1], a_addr(sbase + OFF_AHI, arow + 16, akb));
                    uint32_t sbuf = slotbase + (uint32_t)sub * 8192u;
                    int msel = lane >> 3, r8 = lane & 7;
                    uint32_t brow_off = (uint32_t)(warp_n * 64 + ((msel >> 1) << 3) + r8) * 16u
                                      + (uint32_t)(msel & 1) * 4096u;
                    #pragma unroll
                    for (int p = 0; p < 4; ++p) {
                        uint32_t bh[4];
                        ldsm4(bh, sbuf + brow_off + (uint32_t)p * 256u);
                        #pragma unroll
                        for (int mt = 0; mt < 2; ++mt) {
                            mma16816h(acc[mt][2 * p],     ah[mt], bh[0], bh[1]);
                            mma16816h(acc[mt][2 * p + 1], ah[mt], bh[2], bh[3]);
                        }
                    }
                }
            }

            // ---- cell for this half ----
            const int odd = lane & 1;
            #pragma unroll
            for (int mt = 0; mt < 2; ++mt) {
                #pragma unroll
                for (int nt = 0; nt < 8; ++nt) {
                    float c0v = acc[mt][nt][0], c1v = acc[mt][nt][1];
                    float c2v = acc[mt][nt][2], c3v = acc[mt][nt][3];
                    float e0 = __shfl_xor_sync(0xffffffffu, c0v, 1);
                    float e1 = __shfl_xor_sync(0xffffffffu, c1v, 1);
                    float e2 = __shfl_xor_sync(0xffffffffu, c2v, 1);
                    float e3 = __shfl_xor_sync(0xffffffffu, c3v, 1);
                    int mrow = warp_m * 32 + mt * 16 + (lane >> 2) + (odd ? 8 : 0);
                    int rl   = warp_n * 16 + nt * 2 + ((lane & 3) >> 1);
                    int r    = nh * 64 + rl;
                    float zi = (odd ? e2 : c0v) + sBias[r];
                    float zf = (odd ? e3 : c1v) + sBias[128 + r];
                    float zg = (odd ? c2v : e0) + sBias[256 + r];
                    float zo = (odd ? c3v : e1) + sBias[384 + r];
                    float co = sC[mrow * 128 + r];
                    float cn = fmaf(sig_t(zf), co, sig_t(zi) * tanh_a(zg));
                    float hn = sig_t(zo) * tanh_a(cn);
                    int msk = sMask[mrow];
                    if (msk) sC[mrow * 128 + r] = cn;
                    if (nh == 0) {
                        hpend[mt * 8 + nt] = hn;
                    } else if (msk) {
                        uint32_t aH = a_addr(sbase + OFF_AHI, mrow, 128 + 2 * r);
                        __half bh16 = __float2half_rn(hn);
                        asm volatile("st.shared.b16 [%0], %1;" :: "r"(aH), "h"(*(uint16_t*)&bh16));
                    }
                }
            }
        }

        // flush pending half-0 h writes (GEMMs done reading A)
        #pragma unroll
        for (int mt = 0; mt < 2; ++mt) {
            #pragma unroll
            for (int nt = 0; nt < 8; ++nt) {
                int mrow = warp_m * 32 + mt * 16 + (lane >> 2) + ((lane & 1) ? 8 : 0);
                int r    = warp_n * 16 + nt * 2 + ((lane & 3) >> 1);
                if (sMask[mrow]) {
                    uint32_t aH = a_addr(sbase + OFF_AHI, mrow, 128 + 2 * r);
                    __half bh16 = __float2half_rn(hpend[mt * 8 + nt]);
                    asm volatile("st.shared.b16 [%0], %1;" :: "r"(aH), "h"(*(uint16_t*)&bh16));
                }
            }
        }
        __syncthreads();     // h_t complete in A plane

        // ---- fused output head: warps 0-3, one m16 tile each; K=128, N=8 (5 used) ----
        if (wid < 4) {
            float oacc[4] = {0.f, 0.f, 0.f, 0.f};
            uint32_t wbase = sbase + OFF_WOUT + (uint32_t)(lane >> 2) * 256u
                           + (uint32_t)(lane & 3) * 4u;
            int arow = wid * 16 + (lane & 15);
            #pragma unroll
            for (int kc = 0; kc < 8; ++kc) {
                uint32_t ah[4];
                int akb = 128 + kc * 32 + ((lane >> 4) << 4);
                ldsm4(ah, a_addr(sbase + OFF_AHI, arow, akb));
                uint32_t b0, b1;
                asm volatile("ld.shared.b32 %0, [%1];" : "=r"(b0) : "r"(wbase + kc * 32u));
                asm volatile("ld.shared.b32 %0, [%1];" : "=r"(b1) : "r"(wbase + kc * 32u + 16u));
                mma16816h(oacc, ah, b0, b1);
            }
            int r0 = wid * 16 + (lane >> 2);
            int cn0 = (lane & 3) * 2;
            int m0 = sMask[r0], m1 = sMask[r0 + 8];
            float* yp0 = &out_y[((size_t)st * N_SEQ + n0 + r0) * OUT_DIM];
            float* yp1 = &out_y[((size_t)st * N_SEQ + n0 + r0 + 8) * OUT_DIM];
            if (cn0 < OUT_DIM) {
                yp0[cn0] = m0 ? oacc[0] + sBout[cn0] : 0.f;
                yp1[cn0] = m1 ? oacc[2] + sBout[cn0] : 0.f;
            }
            if (cn0 + 1 < OUT_DIM) {
                yp0[cn0 + 1] = m0 ? oacc[1] + sBout[cn0 + 1] : 0.f;
                yp1[cn0 + 1] = m1 ? oacc[3] + sBout[cn0 + 1] : 0.f;
            }
        }
        __syncthreads();     // head done with sMask/A before next restage
    }

    // ---- final h, c writeback ----
    {
        int m = t >> 2, rblk = (t & 3) * 32;
        float4* hp = (float4*)&out_h[(size_t)(n0 + m) * RDIM + rblk];
        float4* cp = (float4*)&out_c[(size_t)(n0 + m) * RDIM + rblk];
        #pragma unroll
        for (int jj = 0; jj < 8; ++jj) {
            int r0 = rblk + jj * 4;
            uint32_t vh0, vh1;
            uint32_t aH0 = a_addr(sbase + OFF_AHI, m, 128 + 2 * r0);
            uint32_t aH1 = a_addr(sbase + OFF_AHI, m, 128 + 2 * r0 + 4);
            asm volatile("ld.shared.b32 %0, [%1];" : "=r"(vh0) : "r"(aH0));
            asm volatile("ld.shared.b32 %0, [%1];" : "=r"(vh1) : "r"(aH1));
            __half2 h2a = *reinterpret_cast<__half2*>(&vh0);
            __half2 h2b = *reinterpret_cast<__half2*>(&vh1);
            float4 hv;
            hv.x = __half2float(h2a.x);
            hv.y = __half2float(h2a.y);
            hv.z = __half2float(h2b.x);
            hv.w = __half2float(h2b.y);
            hp[jj] = hv;
            cp[jj] = *(float4*)&sC[m * 128 + r0];
        }
    }
}

extern "C" void kernel_launch(void* const* d_in, const int* in_sizes, int n_in,
                              void* d_out, int out_size) {
    const float* input_data = (const float*)d_in[0];
    const float* h0         = (const float*)d_in[1];
    const float* c0         = (const float*)d_in[2];
    const int*   ped        = (const int*)  d_in[3];
    const float* W_emb      = (const float*)d_in[4];
    const float* b_emb      = (const float*)d_in[5];
    const float* W_ih       = (const float*)d_in[6];
    const float* W_hh       = (const float*)d_in[7];
    const float* b_ih       = (const float*)d_in[8];
    const float* b_hh       = (const float*)d_in[9];
    const float* W_out      = (const float*)d_in[10];
    const float* b_out      = (const float*)d_in[11];

    float* out   = (float*)d_out;
    float* out_y = out;                                      // [S][N][5]
    float* out_h = out + (size_t)S_LEN * N_SEQ * OUT_DIM;    // [N][128]
    float* out_c = out_h + (size_t)N_SEQ * RDIM;             // [N][128]

    prep_w<<<48, 128>>>(W_ih, W_hh);
    prep_bias<<<1, 512>>>(b_ih, b_hh);

    cudaFuncSetAttribute(lstm_mma, cudaFuncAttributeMaxDynamicSharedMemorySize, SMEM_TOTAL);
    lstm_mma<<<N_SEQ / TILE, NTHREADS, SMEM_TOTAL>>>(
        input_data, h0, c0, ped, W_emb, b_emb, W_out, b_out, out_y, out_h, out_c);
}